// round 14
// baseline (speedup 1.0000x reference)
#include <cuda_runtime.h>
#include <cuda_fp16.h>
#include <cstdint>

// Problem: B=4, T=4096, C=384 (n_embd), H=16 (head_size)
// out[b,t,:] = softmax_causal( (x@Wq)(x@Wk)^T / sqrt(H) ) @ (x@Wv)

#define B_     4
#define T_     4096
#define C_     384
#define H_     16
#define BT_    (B_ * T_)
#define SPLITS 8

// fp16 hi/lo planes. q pre-scaled by H^-0.5 * log2(e). q,k: [token][16h].
// v: [b][h][t] (transposed).
__device__ uint4 g_qh_[BT_ * 2];
__device__ uint4 g_ql_[BT_ * 2];
__device__ uint4 g_kh_[BT_ * 2];
__device__ uint4 g_kl_[BT_ * 2];
__device__ uint4 g_vh_[B_ * 16 * T_ / 8];
__device__ uint4 g_vl_[B_ * 16 * T_ / 8];
__device__ float g_pacc[(size_t)SPLITS * BT_ * H_];
__device__ float g_pl[SPLITS * BT_];
__device__ int   g_cnt[B_ * (T_ / 32)];     // zero-init; self-resetting
// W fragments: [kk=24][nt=6][r=2][plane=2][lane=32] fp16x2 (36 KB)
__device__ unsigned g_wfrag[24 * 6 * 2 * 2 * 32];

// ---------------- helpers ----------------
__device__ __forceinline__ float ex2(float x) {
    float y; asm("ex2.approx.ftz.f32 %0, %1;" : "=f"(y) : "f"(x)); return y;
}
__device__ __forceinline__ void cp16(unsigned s, const void* g) {
    asm volatile("cp.async.cg.shared.global [%0], [%1], 16;" :: "r"(s), "l"(g));
}
__device__ __forceinline__ unsigned packh2(float hi, float lo) {
    unsigned r; asm("cvt.rn.f16x2.f32 %0, %1, %2;" : "=r"(r) : "f"(hi), "f"(lo)); return r;
}
__device__ __forceinline__ unsigned pack2h(__half a, __half b) {  // a = lower
    return (unsigned)__half_as_ushort(a) | ((unsigned)__half_as_ushort(b) << 16);
}
__device__ __forceinline__ void split16(float x, __half& hi, __half& lo) {
    hi = __float2half_rn(x);
    lo = __float2half_rn(x - __half2float(hi));
}
__device__ __forceinline__ void mma16816(float* d, const unsigned* a, const unsigned* b) {
    asm volatile(
        "mma.sync.aligned.m16n8k16.row.col.f32.f16.f16.f32 "
        "{%0,%1,%2,%3}, {%4,%5,%6,%7}, {%8,%9}, {%0,%1,%2,%3};"
        : "+f"(d[0]), "+f"(d[1]), "+f"(d[2]), "+f"(d[3])
        : "r"(a[0]), "r"(a[1]), "r"(a[2]), "r"(a[3]), "r"(b[0]), "r"(b[1]));
}

// ---------------------------------------------------------------------------
// Kernel 0: W prep — fragment-exact hi/lo fp16 W tiles (unchanged).
// ---------------------------------------------------------------------------
__global__ __launch_bounds__(256)
void prep_kernel(const float* __restrict__ Wk,
                 const float* __restrict__ Wq,
                 const float* __restrict__ Wv) {
    const int idx = blockIdx.x * 256 + threadIdx.x;
    const int lane = idx & 31;
    const int pl = (idx >> 5) & 1;
    const int r  = (idx >> 6) & 1;
    const int rem = idx >> 7;
    const int nt = rem % 6;
    const int kk = rem / 6;
    const int gg = lane >> 2, tg = lane & 3;
    const int n  = nt * 8 + gg;
    const int k0 = kk * 16 + 2 * tg + r * 8;

    const float* Ws = (n < 16) ? Wk : ((n < 32) ? Wq : Wv);
    const int h = n & 15;
    const float s = (n >= 16 && n < 32) ? (0.25f * 1.4426950408889634f) : 1.0f;
    float v0 = Ws[k0 * 16 + h] * s;
    float v1 = Ws[(k0 + 1) * 16 + h] * s;
    __half h0, l0, h1, l1;
    split16(v0, h0, l0); split16(v1, h1, l1);
    g_wfrag[idx] = pl ? pack2h(l0, l1) : pack2h(h0, h1);
}

// ---------------------------------------------------------------------------
// Kernel 1: tensor-core QKV projection. 512 blocks x 64 threads (2 warps);
// depth-4 A prefetch for more DRAM MLP + better block distribution.
// ---------------------------------------------------------------------------
__global__ __launch_bounds__(64, 8)
void proj_mma(const float* __restrict__ x) {
    const int tid  = threadIdx.x;
    const int w    = tid >> 5;
    const int lane = tid & 31;
    const int g    = lane >> 2, tig = lane & 3;
    const int row0 = blockIdx.x * 32 + w * 16;
    const int ra = row0 + g, rb = ra + 8;

    const float* pa = x + (size_t)ra * C_ + 2 * tig;
    const float* pb = x + (size_t)rb * C_ + 2 * tig;

    float D[6][4];
#pragma unroll
    for (int nt = 0; nt < 6; nt++)
#pragma unroll
        for (int e = 0; e < 4; e++) D[nt][e] = 0.f;

    auto loadA = [&](float2* d, int kk) {
        d[0] = *(const float2*)(pa + kk * 16);
        d[1] = *(const float2*)(pb + kk * 16);
        d[2] = *(const float2*)(pa + kk * 16 + 8);
        d[3] = *(const float2*)(pb + kk * 16 + 8);
    };

    float2 c0[4], c1[4], c2[4], c3[4];
    loadA(c0, 0); loadA(c1, 1); loadA(c2, 2); loadA(c3, 3);

#pragma unroll 4
    for (int kk = 0; kk < 24; kk++) {
        float2 c4[4];
        if (kk + 4 < 24) loadA(c4, kk + 4);

        unsigned ah[4], al[4];
#pragma unroll
        for (int p = 0; p < 4; p++) {
            __half h0, l0, h1, l1;
            split16(c0[p].x, h0, l0);
            split16(c0[p].y, h1, l1);
            ah[p] = pack2h(h0, h1);
            al[p] = pack2h(l0, l1);
        }

        const unsigned* wkb = g_wfrag + kk * 768 + lane;
#pragma unroll
        for (int nt = 0; nt < 6; nt++) {
            const unsigned* wn = wkb + nt * 128;
            unsigned bh[2], bl[2];
            bh[0] = wn[0];   bl[0] = wn[32];
            bh[1] = wn[64];  bl[1] = wn[96];
            mma16816(D[nt], ah, bh);
            mma16816(D[nt], al, bh);
            mma16816(D[nt], ah, bl);
        }
#pragma unroll
        for (int p = 0; p < 4; p++) { c0[p] = c1[p]; c1[p] = c2[p]; c2[p] = c3[p]; c3[p] = c4[p]; }
    }

    // ---- epilogue: split16 + attention layouts ----
    const int bb = ra >> 12;
    unsigned* kh = (unsigned*)g_kh_;
    unsigned* kl = (unsigned*)g_kl_;
    unsigned* qh = (unsigned*)g_qh_;
    unsigned* ql = (unsigned*)g_ql_;
    __half* vh = (__half*)g_vh_;
    __half* vl = (__half*)g_vl_;

#pragma unroll
    for (int rr = 0; rr < 2; rr++) {
        const int token = rr ? rb : ra;
        const int e0 = rr * 2;
        __half h0, l0, h1, l1;

        split16(D[0][e0], h0, l0); split16(D[0][e0+1], h1, l1);
        kh[token * 8 + tig]     = pack2h(h0, h1);
        kl[token * 8 + tig]     = pack2h(l0, l1);
        split16(D[1][e0], h0, l0); split16(D[1][e0+1], h1, l1);
        kh[token * 8 + tig + 4] = pack2h(h0, h1);
        kl[token * 8 + tig + 4] = pack2h(l0, l1);

        split16(D[2][e0], h0, l0); split16(D[2][e0+1], h1, l1);
        qh[token * 8 + tig]     = pack2h(h0, h1);
        ql[token * 8 + tig]     = pack2h(l0, l1);
        split16(D[3][e0], h0, l0); split16(D[3][e0+1], h1, l1);
        qh[token * 8 + tig + 4] = pack2h(h0, h1);
        ql[token * 8 + tig + 4] = pack2h(l0, l1);

        const int t = token & (T_ - 1);
#pragma unroll
        for (int nv = 0; nv < 2; nv++) {
            const int hb = bb * 16 + nv * 8 + 2 * tig;
            split16(D[4 + nv][e0],   h0, l0);
            split16(D[4 + nv][e0+1], h1, l1);
            vh[(size_t)hb * T_ + t]       = h0;
            vl[(size_t)hb * T_ + t]       = l0;
            vh[(size_t)(hb + 1) * T_ + t] = h1;
            vl[(size_t)(hb + 1) * T_ + t] = l1;
        }
    }
}

// ---------------------------------------------------------------------------
// Kernel 2: tensor-core causal flash attention. SPLITS=8; row sums via a
// ones-fragment MMA on the P fragment (no FADD chain, no shuffles). The
// last split block of each (tile,b) — tracked by an atomic counter —
// performs the final cross-split reduction and writes out.
// ---------------------------------------------------------------------------
__global__ __launch_bounds__(128, 4)
void attn_kernel(float* __restrict__ out) {
    __shared__ __align__(16) char sbuf[4 * 6144];
    __shared__ int s_last;

    const int tid  = threadIdx.x;
    const int w    = tid >> 5;
    const int lane = tid & 31;
    const int g    = lane >> 2;
    const int tig  = lane & 3;
    const int b    = blockIdx.z;
    const int split = blockIdx.y;
    const int tile  = (int)gridDim.x - 1 - (int)blockIdx.x;  // heavy-first
    const int q_start = tile * 32;
    const int n_keys = q_start + 32;
    const int len = ((n_keys + 16 * SPLITS - 1) / (16 * SPLITS)) * 16;
    const int kb  = split * len;
    const int ke  = min(kb + len, n_keys);

    unsigned qh[2][4], ql[2][4];
    {
        const char* qhb = (const char*)g_qh_;
        const char* qlb = (const char*)g_ql_;
        const size_t qrow0 = (size_t)b * T_ + q_start;
#pragma unroll
        for (int mt = 0; mt < 2; mt++)
#pragma unroll
            for (int p4 = 0; p4 < 4; p4++) {
                int roff = mt * 16 + g + ((p4 & 1) << 3);
                int hoff = tig * 2 + ((p4 >> 1) << 3);
                size_t off = (qrow0 + roff) * 32 + hoff * 2;
                qh[mt][p4] = *(const unsigned*)(qhb + off);
                ql[mt][p4] = *(const unsigned*)(qlb + off);
            }
    }

    float Do[2][2][4];
    float Dl[2][4];                       // row-sum accumulators (ones-MMA)
#pragma unroll
    for (int a = 0; a < 2; a++) {
#pragma unroll
        for (int c = 0; c < 2; c++)
#pragma unroll
            for (int e = 0; e < 4; e++) Do[a][c][e] = 0.f;
#pragma unroll
        for (int e = 0; e < 4; e++) Dl[a][e] = 0.f;
    }
    const unsigned ones[2] = {0x3C003C00u, 0x3C003C00u};   // fp16 1.0 x2

    char* wb = sbuf + w * 6144;
    const __half* khg = (const __half*)g_kh_ + (size_t)b * T_ * 16;
    const __half* klg = (const __half*)g_kl_ + (size_t)b * T_ * 16;
    const __half* vhg = (const __half*)g_vh_ + (size_t)b * 16 * T_;
    const __half* vlg = (const __half*)g_vl_ + (size_t)b * 16 * T_;

    auto load_chunk = [&](int bf, int t0) {
        unsigned sa = (unsigned)__cvta_generic_to_shared(wb + bf * 3072);
        const int e = lane >> 1;
        const int hf = lane & 1;
        cp16(sa +        (unsigned)(e * 48 + hf * 16), khg + (size_t)(t0 + e) * 16 + hf * 8);
        cp16(sa + 768u  + (unsigned)(e * 48 + hf * 16), klg + (size_t)(t0 + e) * 16 + hf * 8);
        cp16(sa + 1536u + (unsigned)(e * 48 + hf * 16), vhg + (size_t)e * T_ + t0 + hf * 8);
        cp16(sa + 2304u + (unsigned)(e * 48 + hf * 16), vlg + (size_t)e * T_ + t0 + hf * 8);
        asm volatile("cp.async.commit_group;");
    };

    auto compute = [&](int bf, int t0, bool masked) {
        const char* kh_s = wb + bf * 3072;
        const char* kl_s = kh_s + 768;
        const char* vh_s = kh_s + 1536;
        const char* vl_s = kh_s + 2304;

        unsigned khb[2][2], klb[2][2], vhb[2][2], vlb[2][2];
#pragma unroll
        for (int nt = 0; nt < 2; nt++) {
            int key = g + nt * 8;
            khb[nt][0] = *(const unsigned*)(kh_s + key * 48 + tig * 4);
            khb[nt][1] = *(const unsigned*)(kh_s + key * 48 + 16 + tig * 4);
            klb[nt][0] = *(const unsigned*)(kl_s + key * 48 + tig * 4);
            klb[nt][1] = *(const unsigned*)(kl_s + key * 48 + 16 + tig * 4);
            int h = g + nt * 8;
            vhb[nt][0] = *(const unsigned*)(vh_s + h * 48 + tig * 4);
            vhb[nt][1] = *(const unsigned*)(vh_s + h * 48 + 16 + tig * 4);
            vlb[nt][0] = *(const unsigned*)(vl_s + h * 48 + tig * 4);
            vlb[nt][1] = *(const unsigned*)(vl_s + h * 48 + 16 + tig * 4);
        }

#pragma unroll
        for (int mt = 0; mt < 2; mt++) {
            float ds[2][4];
#pragma unroll
            for (int nt = 0; nt < 2; nt++) {
#pragma unroll
                for (int e = 0; e < 4; e++) ds[nt][e] = 0.f;
                mma16816(ds[nt], qh[mt], khb[nt]);
                mma16816(ds[nt], qh[mt], klb[nt]);
                mma16816(ds[nt], ql[mt], khb[nt]);
            }
            const int rowq0 = q_start + mt * 16 + g;
#pragma unroll
            for (int nt = 0; nt < 2; nt++) {
                const int kc = t0 + nt * 8 + 2 * tig;
#pragma unroll
                for (int e = 0; e < 4; e++) {
                    float p = ex2(ds[nt][e]);
                    if (masked) {
                        int key = kc + (e & 1);
                        int rq  = rowq0 + ((e >> 1) << 3);
                        p = (key <= rq) ? p : 0.f;
                    }
                    ds[nt][e] = p;
                }
            }
            unsigned pa[4];
            pa[0] = packh2(ds[0][1], ds[0][0]);
            pa[1] = packh2(ds[0][3], ds[0][2]);
            pa[2] = packh2(ds[1][1], ds[1][0]);
            pa[3] = packh2(ds[1][3], ds[1][2]);
            mma16816(Dl[mt], pa, ones);    // row sums (all D cols identical)
#pragma unroll
            for (int nh = 0; nh < 2; nh++) {
                mma16816(Do[mt][nh], pa, vhb[nh]);
                mma16816(Do[mt][nh], pa, vlb[nh]);
            }
        }
    };

    int t0 = kb + w * 16;
    if (t0 < ke) {
        load_chunk(0, t0);
        int bf = 0;
        while (t0 < ke) {
            int tn = t0 + 64;     // this warp's next chunk (stride 4 warps)
            if (tn < ke) {
                load_chunk(bf ^ 1, tn);
                asm volatile("cp.async.wait_group 1;");
            } else {
                asm volatile("cp.async.wait_group 0;");
            }
            __syncwarp();
            compute(bf, t0, t0 >= q_start);
            __syncwarp();
            bf ^= 1; t0 = tn;
        }
    }

    // ---- in-block reduction across the 4 warps ----
    __syncthreads();
    float* sred = (float*)sbuf;            // [4][32][16]
    float* sl   = (float*)(sbuf + 8192);   // [4][32]
#pragma unroll
    for (int mt = 0; mt < 2; mt++) {
#pragma unroll
        for (int nt = 0; nt < 2; nt++)
#pragma unroll
            for (int e = 0; e < 4; e++) {
                int rl = mt * 16 + g + ((e >> 1) << 3);
                int cl = nt * 8 + tig * 2 + (e & 1);
                sred[(w * 32 + rl) * 16 + cl] = Do[mt][nt][e];
            }
        if (tig == 0) {
            sl[w * 32 + mt * 16 + g]     = Dl[mt][0];
            sl[w * 32 + mt * 16 + g + 8] = Dl[mt][2];
        }
    }
    __syncthreads();

    const int row = tid >> 2;
    const int cg  = tid & 3;
    {
        float4 a = make_float4(0.f, 0.f, 0.f, 0.f);
#pragma unroll
        for (int ww = 0; ww < 4; ww++) {
            float4 t = *(const float4*)&sred[(ww * 32 + row) * 16 + cg * 4];
            a.x += t.x; a.y += t.y; a.z += t.z; a.w += t.w;
        }
        const size_t prow = (size_t)split * BT_ + (size_t)b * T_ + q_start + row;
        ((float4*)(g_pacc + prow * 16))[cg] = a;
        if (cg == 0) {
            float ls = sl[row] + sl[32 + row] + sl[64 + row] + sl[96 + row];
            g_pl[prow] = ls;
        }
    }

    // ---- last-block cross-split reduction ----
    __threadfence();
    if (tid == 0) {
        int old = atomicAdd(&g_cnt[b * (T_ / 32) + tile], 1);
        s_last = (old == SPLITS - 1) ? 1 : 0;
    }
    __syncthreads();
    if (s_last) {
        __threadfence();
        const size_t base = (size_t)b * T_ + q_start + row;
        float l_tot = 0.f;
#pragma unroll
        for (int s = 0; s < SPLITS; s++)
            l_tot += __ldcg(&g_pl[(size_t)s * BT_ + base]);
        const float inv = 1.0f / l_tot;

        float4 a = make_float4(0.f, 0.f, 0.f, 0.f);
#pragma unroll
        for (int s = 0; s < SPLITS; s++) {
            float4 t = __ldcg((const float4*)(g_pacc + ((size_t)s * BT_ + base) * 16) + cg);
            a.x += t.x; a.y += t.y; a.z += t.z; a.w += t.w;
        }
        ((float4*)(out + base * 16))[cg] =
            make_float4(a.x * inv, a.y * inv, a.z * inv, a.w * inv);

        __syncthreads();
        if (tid == 0) *(volatile int*)&g_cnt[b * (T_ / 32) + tile] = 0;
    }
}

extern "C" void kernel_launch(void* const* d_in, const int* in_sizes, int n_in,
                              void* d_out, int out_size) {
    const float* x  = (const float*)d_in[0];
    const float* Wk = (const float*)d_in[1];
    const float* Wq = (const float*)d_in[2];
    const float* Wv = (const float*)d_in[3];
    float* out = (float*)d_out;

    prep_kernel<<<144, 256>>>(Wk, Wq, Wv);
    proj_mma<<<BT_ / 32, 64>>>(x);
    attn_kernel<<<dim3(T_ / 32, SPLITS, B_), 128>>>(out);
}

// round 15
// speedup vs baseline: 1.1001x; 1.1001x over previous
#include <cuda_runtime.h>
#include <cuda_fp16.h>
#include <cstdint>

// Problem: B=4, T=4096, C=384 (n_embd), H=16 (head_size)
// out[b,t,:] = softmax_causal( (x@Wq)(x@Wk)^T / sqrt(H) ) @ (x@Wv)

#define B_     4
#define T_     4096
#define C_     384
#define H_     16
#define BT_    (B_ * T_)
#define SPLITS 4

// fp16 hi/lo planes. q pre-scaled by H^-0.5 * log2(e). q,k: [token][16h].
// v: [b][h][t] (transposed).
__device__ uint4 g_qh_[BT_ * 2];
__device__ uint4 g_ql_[BT_ * 2];
__device__ uint4 g_kh_[BT_ * 2];
__device__ uint4 g_kl_[BT_ * 2];
__device__ uint4 g_vh_[B_ * 16 * T_ / 8];
__device__ uint4 g_vl_[B_ * 16 * T_ / 8];
__device__ float g_pacc[(size_t)SPLITS * BT_ * H_];
__device__ float g_pl[SPLITS * BT_];
// W fragments: [kk=24][nt=6][r=2][plane=2][lane=32] fp16x2 (36 KB)
__device__ unsigned g_wfrag[24 * 6 * 2 * 2 * 32];

// ---------------- helpers ----------------
__device__ __forceinline__ float ex2(float x) {
    float y; asm("ex2.approx.ftz.f32 %0, %1;" : "=f"(y) : "f"(x)); return y;
}
__device__ __forceinline__ void cp16(unsigned s, const void* g) {
    asm volatile("cp.async.cg.shared.global [%0], [%1], 16;" :: "r"(s), "l"(g));
}
__device__ __forceinline__ unsigned packh2(float hi, float lo) {
    unsigned r; asm("cvt.rn.f16x2.f32 %0, %1, %2;" : "=r"(r) : "f"(hi), "f"(lo)); return r;
}
__device__ __forceinline__ unsigned pack2h(__half a, __half b) {  // a = lower
    return (unsigned)__half_as_ushort(a) | ((unsigned)__half_as_ushort(b) << 16);
}
__device__ __forceinline__ void split16(float x, __half& hi, __half& lo) {
    hi = __float2half_rn(x);
    lo = __float2half_rn(x - __half2float(hi));
}
__device__ __forceinline__ void mma16816(float* d, const unsigned* a, const unsigned* b) {
    asm volatile(
        "mma.sync.aligned.m16n8k16.row.col.f32.f16.f16.f32 "
        "{%0,%1,%2,%3}, {%4,%5,%6,%7}, {%8,%9}, {%0,%1,%2,%3};"
        : "+f"(d[0]), "+f"(d[1]), "+f"(d[2]), "+f"(d[3])
        : "r"(a[0]), "r"(a[1]), "r"(a[2]), "r"(a[3]), "r"(b[0]), "r"(b[1]));
}

// ---------------------------------------------------------------------------
// Kernel 0: W prep — fragment-exact hi/lo fp16 W tiles (unchanged R12).
// ---------------------------------------------------------------------------
__global__ __launch_bounds__(256)
void prep_kernel(const float* __restrict__ Wk,
                 const float* __restrict__ Wq,
                 const float* __restrict__ Wv) {
    const int idx = blockIdx.x * 256 + threadIdx.x;
    const int lane = idx & 31;
    const int pl = (idx >> 5) & 1;
    const int r  = (idx >> 6) & 1;
    const int rem = idx >> 7;
    const int nt = rem % 6;
    const int kk = rem / 6;
    const int gg = lane >> 2, tg = lane & 3;
    const int n  = nt * 8 + gg;
    const int k0 = kk * 16 + 2 * tg + r * 8;

    const float* Ws = (n < 16) ? Wk : ((n < 32) ? Wq : Wv);
    const int h = n & 15;
    const float s = (n >= 16 && n < 32) ? (0.25f * 1.4426950408889634f) : 1.0f;
    float v0 = Ws[k0 * 16 + h] * s;
    float v1 = Ws[(k0 + 1) * 16 + h] * s;
    __half h0, l0, h1, l1;
    split16(v0, h0, l0); split16(v1, h1, l1);
    g_wfrag[idx] = pl ? pack2h(l0, l1) : pack2h(h0, h1);
}

// ---------------------------------------------------------------------------
// Kernel 1: tensor-core QKV projection (R13 config: 256 blocks x 128 thr,
// depth-3 A prefetch).
// ---------------------------------------------------------------------------
__global__ __launch_bounds__(128, 4)
void proj_mma(const float* __restrict__ x) {
    const int tid  = threadIdx.x;
    const int w    = tid >> 5;
    const int lane = tid & 31;
    const int g    = lane >> 2, tig = lane & 3;
    const int row0 = blockIdx.x * 64 + w * 16;
    const int ra = row0 + g, rb = ra + 8;

    const float* pa = x + (size_t)ra * C_ + 2 * tig;
    const float* pb = x + (size_t)rb * C_ + 2 * tig;

    float D[6][4];
#pragma unroll
    for (int nt = 0; nt < 6; nt++)
#pragma unroll
        for (int e = 0; e < 4; e++) D[nt][e] = 0.f;

    auto loadA = [&](float2* d, int kk) {
        d[0] = *(const float2*)(pa + kk * 16);
        d[1] = *(const float2*)(pb + kk * 16);
        d[2] = *(const float2*)(pa + kk * 16 + 8);
        d[3] = *(const float2*)(pb + kk * 16 + 8);
    };

    float2 c0[4], c1[4], c2[4];
    loadA(c0, 0);
    loadA(c1, 1);
    loadA(c2, 2);

#pragma unroll 3
    for (int kk = 0; kk < 24; kk++) {
        float2 c3[4];
        if (kk + 3 < 24) loadA(c3, kk + 3);

        unsigned ah[4], al[4];
#pragma unroll
        for (int p = 0; p < 4; p++) {
            __half h0, l0, h1, l1;
            split16(c0[p].x, h0, l0);
            split16(c0[p].y, h1, l1);
            ah[p] = pack2h(h0, h1);
            al[p] = pack2h(l0, l1);
        }

        const unsigned* wkb = g_wfrag + kk * 768 + lane;
#pragma unroll
        for (int nt = 0; nt < 6; nt++) {
            const unsigned* wn = wkb + nt * 128;
            unsigned bh[2], bl[2];
            bh[0] = wn[0];   bl[0] = wn[32];
            bh[1] = wn[64];  bl[1] = wn[96];
            mma16816(D[nt], ah, bh);
            mma16816(D[nt], al, bh);
            mma16816(D[nt], ah, bl);
        }
#pragma unroll
        for (int p = 0; p < 4; p++) { c0[p] = c1[p]; c1[p] = c2[p]; c2[p] = c3[p]; }
    }

    // ---- epilogue: split16 + attention layouts ----
    const int bb = ra >> 12;
    unsigned* kh = (unsigned*)g_kh_;
    unsigned* kl = (unsigned*)g_kl_;
    unsigned* qh = (unsigned*)g_qh_;
    unsigned* ql = (unsigned*)g_ql_;
    __half* vh = (__half*)g_vh_;
    __half* vl = (__half*)g_vl_;

#pragma unroll
    for (int rr = 0; rr < 2; rr++) {
        const int token = rr ? rb : ra;
        const int e0 = rr * 2;
        __half h0, l0, h1, l1;

        split16(D[0][e0], h0, l0); split16(D[0][e0+1], h1, l1);
        kh[token * 8 + tig]     = pack2h(h0, h1);
        kl[token * 8 + tig]     = pack2h(l0, l1);
        split16(D[1][e0], h0, l0); split16(D[1][e0+1], h1, l1);
        kh[token * 8 + tig + 4] = pack2h(h0, h1);
        kl[token * 8 + tig + 4] = pack2h(l0, l1);

        split16(D[2][e0], h0, l0); split16(D[2][e0+1], h1, l1);
        qh[token * 8 + tig]     = pack2h(h0, h1);
        ql[token * 8 + tig]     = pack2h(l0, l1);
        split16(D[3][e0], h0, l0); split16(D[3][e0+1], h1, l1);
        qh[token * 8 + tig + 4] = pack2h(h0, h1);
        ql[token * 8 + tig + 4] = pack2h(l0, l1);

        const int t = token & (T_ - 1);
#pragma unroll
        for (int nv = 0; nv < 2; nv++) {
            const int hb = bb * 16 + nv * 8 + 2 * tig;
            split16(D[4 + nv][e0],   h0, l0);
            split16(D[4 + nv][e0+1], h1, l1);
            vh[(size_t)hb * T_ + t]       = h0;
            vl[(size_t)hb * T_ + t]       = l0;
            vh[(size_t)(hb + 1) * T_ + t] = h1;
            vl[(size_t)(hb + 1) * T_ + t] = l1;
        }
    }
}

// ---------------------------------------------------------------------------
// Kernel 2: tensor-core causal flash attention (R13 structure: SPLITS=4,
// 3-stage per-warp cp.async pipeline) + ones-MMA row sums (verified in R14).
// ---------------------------------------------------------------------------
__global__ __launch_bounds__(128, 4)
void attn_kernel() {
    // per warp: 3 bufs x 3072 = 9216 B -> 36864 B total
    __shared__ __align__(16) char sbuf[4 * 9216];

    const int tid  = threadIdx.x;
    const int w    = tid >> 5;
    const int lane = tid & 31;
    const int g    = lane >> 2;
    const int tig  = lane & 3;
    const int b    = blockIdx.z;
    const int split = blockIdx.y;
    const int tile  = (int)gridDim.x - 1 - (int)blockIdx.x;  // heavy-first
    const int q_start = tile * 32;
    const int n_keys = q_start + 32;
    const int len = ((n_keys + 16 * SPLITS - 1) / (16 * SPLITS)) * 16;
    const int kb  = split * len;
    const int ke  = min(kb + len, n_keys);

    unsigned qh[2][4], ql[2][4];
    {
        const char* qhb = (const char*)g_qh_;
        const char* qlb = (const char*)g_ql_;
        const size_t qrow0 = (size_t)b * T_ + q_start;
#pragma unroll
        for (int mt = 0; mt < 2; mt++)
#pragma unroll
            for (int p4 = 0; p4 < 4; p4++) {
                int roff = mt * 16 + g + ((p4 & 1) << 3);
                int hoff = tig * 2 + ((p4 >> 1) << 3);
                size_t off = (qrow0 + roff) * 32 + hoff * 2;
                qh[mt][p4] = *(const unsigned*)(qhb + off);
                ql[mt][p4] = *(const unsigned*)(qlb + off);
            }
    }

    float Do[2][2][4];
    float Dl[2][4];                       // row sums via ones-MMA
#pragma unroll
    for (int a = 0; a < 2; a++) {
#pragma unroll
        for (int c = 0; c < 2; c++)
#pragma unroll
            for (int e = 0; e < 4; e++) Do[a][c][e] = 0.f;
#pragma unroll
        for (int e = 0; e < 4; e++) Dl[a][e] = 0.f;
    }
    const unsigned ones[2] = {0x3C003C00u, 0x3C003C00u};   // fp16 1.0 x2

    char* wb = sbuf + w * 9216;
    const __half* khg = (const __half*)g_kh_ + (size_t)b * T_ * 16;
    const __half* klg = (const __half*)g_kl_ + (size_t)b * T_ * 16;
    const __half* vhg = (const __half*)g_vh_ + (size_t)b * 16 * T_;
    const __half* vlg = (const __half*)g_vl_ + (size_t)b * 16 * T_;

    auto load_chunk = [&](int bf, int t0) {
        unsigned sa = (unsigned)__cvta_generic_to_shared(wb + bf * 3072);
        const int e = lane >> 1;
        const int hf = lane & 1;
        cp16(sa +        (unsigned)(e * 48 + hf * 16), khg + (size_t)(t0 + e) * 16 + hf * 8);
        cp16(sa + 768u  + (unsigned)(e * 48 + hf * 16), klg + (size_t)(t0 + e) * 16 + hf * 8);
        cp16(sa + 1536u + (unsigned)(e * 48 + hf * 16), vhg + (size_t)e * T_ + t0 + hf * 8);
        cp16(sa + 2304u + (unsigned)(e * 48 + hf * 16), vlg + (size_t)e * T_ + t0 + hf * 8);
        asm volatile("cp.async.commit_group;");
    };

    auto compute = [&](int bf, int t0, bool masked) {
        const char* kh_s = wb + bf * 3072;
        const char* kl_s = kh_s + 768;
        const char* vh_s = kh_s + 1536;
        const char* vl_s = kh_s + 2304;

        unsigned khb[2][2], klb[2][2], vhb[2][2], vlb[2][2];
#pragma unroll
        for (int nt = 0; nt < 2; nt++) {
            int key = g + nt * 8;
            khb[nt][0] = *(const unsigned*)(kh_s + key * 48 + tig * 4);
            khb[nt][1] = *(const unsigned*)(kh_s + key * 48 + 16 + tig * 4);
            klb[nt][0] = *(const unsigned*)(kl_s + key * 48 + tig * 4);
            klb[nt][1] = *(const unsigned*)(kl_s + key * 48 + 16 + tig * 4);
            int h = g + nt * 8;
            vhb[nt][0] = *(const unsigned*)(vh_s + h * 48 + tig * 4);
            vhb[nt][1] = *(const unsigned*)(vh_s + h * 48 + 16 + tig * 4);
            vlb[nt][0] = *(const unsigned*)(vl_s + h * 48 + tig * 4);
            vlb[nt][1] = *(const unsigned*)(vl_s + h * 48 + 16 + tig * 4);
        }

#pragma unroll
        for (int mt = 0; mt < 2; mt++) {
            float ds[2][4];
#pragma unroll
            for (int nt = 0; nt < 2; nt++) {
#pragma unroll
                for (int e = 0; e < 4; e++) ds[nt][e] = 0.f;
                mma16816(ds[nt], qh[mt], khb[nt]);
                mma16816(ds[nt], qh[mt], klb[nt]);
                mma16816(ds[nt], ql[mt], khb[nt]);
            }
            const int rowq0 = q_start + mt * 16 + g;
#pragma unroll
            for (int nt = 0; nt < 2; nt++) {
                const int kc = t0 + nt * 8 + 2 * tig;
#pragma unroll
                for (int e = 0; e < 4; e++) {
                    float p = ex2(ds[nt][e]);
                    if (masked) {
                        int key = kc + (e & 1);
                        int rq  = rowq0 + ((e >> 1) << 3);
                        p = (key <= rq) ? p : 0.f;
                    }
                    ds[nt][e] = p;
                }
            }
            unsigned pa[4];
            pa[0] = packh2(ds[0][1], ds[0][0]);
            pa[1] = packh2(ds[0][3], ds[0][2]);
            pa[2] = packh2(ds[1][1], ds[1][0]);
            pa[3] = packh2(ds[1][3], ds[1][2]);
            mma16816(Dl[mt], pa, ones);    // row sums (all D cols identical)
#pragma unroll
            for (int nh = 0; nh < 2; nh++) {
                mma16816(Do[mt][nh], pa, vhb[nh]);
                mma16816(Do[mt][nh], pa, vlb[nh]);
            }
        }
    };

    // ---- 3-stage per-warp pipeline (stride = 4 warps x 16 keys) ----
    int t0 = kb + w * 16;
    if (t0 < ke) {
        int pending = 0;
        load_chunk(0, t0); pending++;
        if (t0 + 64 < ke) { load_chunk(1, t0 + 64); pending++; }
        int bf = 0;
        for (; t0 < ke; t0 += 64, bf = (bf == 2 ? 0 : bf + 1)) {
            if (t0 + 128 < ke) {
                load_chunk((bf + 2) % 3, t0 + 128);
                pending++;
            }
            pending--;
            if (pending >= 2)      asm volatile("cp.async.wait_group 2;");
            else if (pending == 1) asm volatile("cp.async.wait_group 1;");
            else                   asm volatile("cp.async.wait_group 0;");
            __syncwarp();
            compute(bf, t0, t0 >= q_start);
            __syncwarp();
        }
    }

    // in-block reduction across the 4 warps
    __syncthreads();
    float* sred = (float*)sbuf;            // [4][32][16]
    float* sl   = (float*)(sbuf + 8192);   // [4][32]
#pragma unroll
    for (int mt = 0; mt < 2; mt++) {
#pragma unroll
        for (int nt = 0; nt < 2; nt++)
#pragma unroll
            for (int e = 0; e < 4; e++) {
                int rl = mt * 16 + g + ((e >> 1) << 3);
                int cl = nt * 8 + tig * 2 + (e & 1);
                sred[(w * 32 + rl) * 16 + cl] = Do[mt][nt][e];
            }
        if (tig == 0) {
            sl[w * 32 + mt * 16 + g]     = Dl[mt][0];
            sl[w * 32 + mt * 16 + g + 8] = Dl[mt][2];
        }
    }
    __syncthreads();

    {
        const int row = tid >> 2;
        const int cg  = tid & 3;
        float4 a = make_float4(0.f, 0.f, 0.f, 0.f);
#pragma unroll
        for (int ww = 0; ww < 4; ww++) {
            float4 t = *(const float4*)&sred[(ww * 32 + row) * 16 + cg * 4];
            a.x += t.x; a.y += t.y; a.z += t.z; a.w += t.w;
        }
        const size_t prow = (size_t)split * BT_ + (size_t)b * T_ + q_start + row;
        ((float4*)(g_pacc + prow * 16))[cg] = a;
        if (cg == 0) {
            float ls = sl[row] + sl[32 + row] + sl[64 + row] + sl[96 + row];
            g_pl[prow] = ls;
        }
    }
}

// ---------------------------------------------------------------------------
// Kernel 3: combine 4 split slots. 4 threads/row, 128-thread blocks.
// ---------------------------------------------------------------------------
__global__ __launch_bounds__(128)
void combine_kernel(float* __restrict__ out) {
    const int idx = blockIdx.x * 128 + threadIdx.x;
    const int row = idx >> 2;
    const int cg  = idx & 3;

    float l = 0.f;
#pragma unroll
    for (int s = 0; s < SPLITS; s++) l += g_pl[(size_t)s * BT_ + row];
    const float inv = 1.0f / l;

    float4 a = make_float4(0.f, 0.f, 0.f, 0.f);
#pragma unroll
    for (int s = 0; s < SPLITS; s++) {
        float4 t = ((const float4*)(g_pacc + ((size_t)s * BT_ + row) * 16))[cg];
        a.x += t.x; a.y += t.y; a.z += t.z; a.w += t.w;
    }
    ((float4*)(out + (size_t)row * 16))[cg] =
        make_float4(a.x * inv, a.y * inv, a.z * inv, a.w * inv);
}

extern "C" void kernel_launch(void* const* d_in, const int* in_sizes, int n_in,
                              void* d_out, int out_size) {
    const float* x  = (const float*)d_in[0];
    const float* Wk = (const float*)d_in[1];
    const float* Wq = (const float*)d_in[2];
    const float* Wv = (const float*)d_in[3];
    float* out = (float*)d_out;

    prep_kernel<<<144, 256>>>(Wk, Wq, Wv);
    proj_mma<<<BT_ / 64, 128>>>(x);
    attn_kernel<<<dim3(T_ / 32, SPLITS, B_), 128>>>();
    combine_kernel<<<BT_ * 4 / 128, 128>>>(out);
}

// round 16
// speedup vs baseline: 1.4976x; 1.3613x over previous
#include <cuda_runtime.h>
#include <cuda_fp16.h>
#include <cstdint>

// Problem: B=4, T=4096, C=384 (n_embd), H=16 (head_size)
// out[b,t,:] = softmax_causal( (x@Wq)(x@Wk)^T / sqrt(H) ) @ (x@Wv)

#define B_     4
#define T_     4096
#define C_     384
#define H_     16
#define BT_    (B_ * T_)
#define SPLITS 4

// q keeps hi/lo split (pre-scaled by H^-0.5*log2 e); k, v are single fp16
// planes (error budget allows). q,k: [token][16h]; v: [b][h][t] transposed.
__device__ uint4 g_qh_[BT_ * 2];
__device__ uint4 g_ql_[BT_ * 2];
__device__ uint4 g_kh_[BT_ * 2];
__device__ uint4 g_vh_[B_ * 16 * T_ / 8];
__device__ float g_pacc[(size_t)SPLITS * BT_ * H_];
__device__ float g_pl[SPLITS * BT_];
// W fragments: [kk=24][nt=6][r=2][plane=2][lane=32] fp16x2 (36 KB)
__device__ unsigned g_wfrag[24 * 6 * 2 * 2 * 32];

// ---------------- helpers ----------------
__device__ __forceinline__ float ex2(float x) {
    float y; asm("ex2.approx.ftz.f32 %0, %1;" : "=f"(y) : "f"(x)); return y;
}
__device__ __forceinline__ void cp16(unsigned s, const void* g) {
    asm volatile("cp.async.cg.shared.global [%0], [%1], 16;" :: "r"(s), "l"(g));
}
__device__ __forceinline__ unsigned packh2(float hi, float lo) {
    unsigned r; asm("cvt.rn.f16x2.f32 %0, %1, %2;" : "=r"(r) : "f"(hi), "f"(lo)); return r;
}
__device__ __forceinline__ unsigned pack2h(__half a, __half b) {  // a = lower
    return (unsigned)__half_as_ushort(a) | ((unsigned)__half_as_ushort(b) << 16);
}
__device__ __forceinline__ void split16(float x, __half& hi, __half& lo) {
    hi = __float2half_rn(x);
    lo = __float2half_rn(x - __half2float(hi));
}
__device__ __forceinline__ void mma16816(float* d, const unsigned* a, const unsigned* b) {
    asm volatile(
        "mma.sync.aligned.m16n8k16.row.col.f32.f16.f16.f32 "
        "{%0,%1,%2,%3}, {%4,%5,%6,%7}, {%8,%9}, {%0,%1,%2,%3};"
        : "+f"(d[0]), "+f"(d[1]), "+f"(d[2]), "+f"(d[3])
        : "r"(a[0]), "r"(a[1]), "r"(a[2]), "r"(a[3]), "r"(b[0]), "r"(b[1]));
}

// ---------------------------------------------------------------------------
// Kernel 0: W prep — fragment-exact hi/lo fp16 W tiles. Grid 288 >= 148
// (avoids the low-grid issue throttle).
// ---------------------------------------------------------------------------
__global__ __launch_bounds__(128)
void prep_kernel(const float* __restrict__ Wk,
                 const float* __restrict__ Wq,
                 const float* __restrict__ Wv) {
    const int idx = blockIdx.x * 128 + threadIdx.x;   // 0..36863
    const int lane = idx & 31;
    const int pl = (idx >> 5) & 1;
    const int r  = (idx >> 6) & 1;
    const int rem = idx >> 7;
    const int nt = rem % 6;
    const int kk = rem / 6;
    const int gg = lane >> 2, tg = lane & 3;
    const int n  = nt * 8 + gg;
    const int k0 = kk * 16 + 2 * tg + r * 8;

    const float* Ws = (n < 16) ? Wk : ((n < 32) ? Wq : Wv);
    const int h = n & 15;
    const float s = (n >= 16 && n < 32) ? (0.25f * 1.4426950408889634f) : 1.0f;
    float v0 = Ws[k0 * 16 + h] * s;
    float v1 = Ws[(k0 + 1) * 16 + h] * s;
    __half h0, l0, h1, l1;
    split16(v0, h0, l0); split16(v1, h1, l1);
    g_wfrag[idx] = pl ? pack2h(l0, l1) : pack2h(h0, h1);
}

// ---------------------------------------------------------------------------
// Kernel 1: tensor-core QKV projection (R13 config). Epilogue writes only
// qh/ql (split) and single-plane kh/vh.
// ---------------------------------------------------------------------------
__global__ __launch_bounds__(128, 4)
void proj_mma(const float* __restrict__ x) {
    const int tid  = threadIdx.x;
    const int w    = tid >> 5;
    const int lane = tid & 31;
    const int g    = lane >> 2, tig = lane & 3;
    const int row0 = blockIdx.x * 64 + w * 16;
    const int ra = row0 + g, rb = ra + 8;

    const float* pa = x + (size_t)ra * C_ + 2 * tig;
    const float* pb = x + (size_t)rb * C_ + 2 * tig;

    float D[6][4];
#pragma unroll
    for (int nt = 0; nt < 6; nt++)
#pragma unroll
        for (int e = 0; e < 4; e++) D[nt][e] = 0.f;

    auto loadA = [&](float2* d, int kk) {
        d[0] = *(const float2*)(pa + kk * 16);
        d[1] = *(const float2*)(pb + kk * 16);
        d[2] = *(const float2*)(pa + kk * 16 + 8);
        d[3] = *(const float2*)(pb + kk * 16 + 8);
    };

    float2 c0[4], c1[4], c2[4];
    loadA(c0, 0);
    loadA(c1, 1);
    loadA(c2, 2);

#pragma unroll 3
    for (int kk = 0; kk < 24; kk++) {
        float2 c3[4];
        if (kk + 3 < 24) loadA(c3, kk + 3);

        unsigned ah[4], al[4];
#pragma unroll
        for (int p = 0; p < 4; p++) {
            __half h0, l0, h1, l1;
            split16(c0[p].x, h0, l0);
            split16(c0[p].y, h1, l1);
            ah[p] = pack2h(h0, h1);
            al[p] = pack2h(l0, l1);
        }

        const unsigned* wkb = g_wfrag + kk * 768 + lane;
#pragma unroll
        for (int nt = 0; nt < 6; nt++) {
            const unsigned* wn = wkb + nt * 128;
            unsigned bh[2], bl[2];
            bh[0] = wn[0];   bl[0] = wn[32];
            bh[1] = wn[64];  bl[1] = wn[96];
            mma16816(D[nt], ah, bh);
            mma16816(D[nt], al, bh);
            mma16816(D[nt], ah, bl);
        }
#pragma unroll
        for (int p = 0; p < 4; p++) { c0[p] = c1[p]; c1[p] = c2[p]; c2[p] = c3[p]; }
    }

    // ---- epilogue ----
    const int bb = ra >> 12;
    unsigned* kh = (unsigned*)g_kh_;
    unsigned* qh = (unsigned*)g_qh_;
    unsigned* ql = (unsigned*)g_ql_;
    __half* vh = (__half*)g_vh_;

#pragma unroll
    for (int rr = 0; rr < 2; rr++) {
        const int token = rr ? rb : ra;
        const int e0 = rr * 2;
        __half h0, l0, h1, l1;

        // K: single plane
        kh[token * 8 + tig]     = packh2(D[0][e0+1], D[0][e0]);
        kh[token * 8 + tig + 4] = packh2(D[1][e0+1], D[1][e0]);

        // Q: hi/lo split (already scaled via W prep)
        split16(D[2][e0], h0, l0); split16(D[2][e0+1], h1, l1);
        qh[token * 8 + tig]     = pack2h(h0, h1);
        ql[token * 8 + tig]     = pack2h(l0, l1);
        split16(D[3][e0], h0, l0); split16(D[3][e0+1], h1, l1);
        qh[token * 8 + tig + 4] = pack2h(h0, h1);
        ql[token * 8 + tig + 4] = pack2h(l0, l1);

        // V: single plane, transposed [b][h][t]
        const int t = token & (T_ - 1);
#pragma unroll
        for (int nv = 0; nv < 2; nv++) {
            const int hb = bb * 16 + nv * 8 + 2 * tig;
            vh[(size_t)hb * T_ + t]       = __float2half_rn(D[4 + nv][e0]);
            vh[(size_t)(hb + 1) * T_ + t] = __float2half_rn(D[4 + nv][e0+1]);
        }
    }
}

// ---------------------------------------------------------------------------
// Kernel 2: tensor-core causal flash attention. Single-plane K/V:
// scores = (qh + ql)·kh (2 MMAs/nt), PV = p·vh. 14 MMAs per 16-key chunk.
// SPLITS=4, 3-stage per-warp cp.async pipeline, ones-MMA row sums.
// ---------------------------------------------------------------------------
__global__ __launch_bounds__(128, 4)
void attn_kernel() {
    // per warp: 3 bufs x (kh 768 | vh 768) = 4608 B -> 18432 B total
    __shared__ __align__(16) char sbuf[4 * 4608];

    const int tid  = threadIdx.x;
    const int w    = tid >> 5;
    const int lane = tid & 31;
    const int g    = lane >> 2;
    const int tig  = lane & 3;
    const int b    = blockIdx.z;
    const int split = blockIdx.y;
    const int tile  = (int)gridDim.x - 1 - (int)blockIdx.x;  // heavy-first
    const int q_start = tile * 32;
    const int n_keys = q_start + 32;
    const int len = ((n_keys + 16 * SPLITS - 1) / (16 * SPLITS)) * 16;
    const int kb  = split * len;
    const int ke  = min(kb + len, n_keys);

    unsigned qh[2][4], ql[2][4];
    {
        const char* qhb = (const char*)g_qh_;
        const char* qlb = (const char*)g_ql_;
        const size_t qrow0 = (size_t)b * T_ + q_start;
#pragma unroll
        for (int mt = 0; mt < 2; mt++)
#pragma unroll
            for (int p4 = 0; p4 < 4; p4++) {
                int roff = mt * 16 + g + ((p4 & 1) << 3);
                int hoff = tig * 2 + ((p4 >> 1) << 3);
                size_t off = (qrow0 + roff) * 32 + hoff * 2;
                qh[mt][p4] = *(const unsigned*)(qhb + off);
                ql[mt][p4] = *(const unsigned*)(qlb + off);
            }
    }

    float Do[2][2][4];
    float Dl[2][4];
#pragma unroll
    for (int a = 0; a < 2; a++) {
#pragma unroll
        for (int c = 0; c < 2; c++)
#pragma unroll
            for (int e = 0; e < 4; e++) Do[a][c][e] = 0.f;
#pragma unroll
        for (int e = 0; e < 4; e++) Dl[a][e] = 0.f;
    }
    const unsigned ones[2] = {0x3C003C00u, 0x3C003C00u};   // fp16 1.0 x2

    char* wb = sbuf + w * 4608;
    const __half* khg = (const __half*)g_kh_ + (size_t)b * T_ * 16;
    const __half* vhg = (const __half*)g_vh_ + (size_t)b * 16 * T_;

    auto load_chunk = [&](int bf, int t0) {
        unsigned sa = (unsigned)__cvta_generic_to_shared(wb + bf * 1536);
        const int e = lane >> 1;
        const int hf = lane & 1;
        cp16(sa +       (unsigned)(e * 48 + hf * 16), khg + (size_t)(t0 + e) * 16 + hf * 8);
        cp16(sa + 768u + (unsigned)(e * 48 + hf * 16), vhg + (size_t)e * T_ + t0 + hf * 8);
        asm volatile("cp.async.commit_group;");
    };

    auto compute = [&](int bf, int t0, bool masked) {
        const char* kh_s = wb + bf * 1536;
        const char* vh_s = kh_s + 768;

        unsigned khb[2][2], vhb[2][2];
#pragma unroll
        for (int nt = 0; nt < 2; nt++) {
            int key = g + nt * 8;
            khb[nt][0] = *(const unsigned*)(kh_s + key * 48 + tig * 4);
            khb[nt][1] = *(const unsigned*)(kh_s + key * 48 + 16 + tig * 4);
            int h = g + nt * 8;
            vhb[nt][0] = *(const unsigned*)(vh_s + h * 48 + tig * 4);
            vhb[nt][1] = *(const unsigned*)(vh_s + h * 48 + 16 + tig * 4);
        }

#pragma unroll
        for (int mt = 0; mt < 2; mt++) {
            float ds[2][4];
#pragma unroll
            for (int nt = 0; nt < 2; nt++) {
#pragma unroll
                for (int e = 0; e < 4; e++) ds[nt][e] = 0.f;
                mma16816(ds[nt], qh[mt], khb[nt]);
                mma16816(ds[nt], ql[mt], khb[nt]);
            }
            const int rowq0 = q_start + mt * 16 + g;
#pragma unroll
            for (int nt = 0; nt < 2; nt++) {
                const int kc = t0 + nt * 8 + 2 * tig;
#pragma unroll
                for (int e = 0; e < 4; e++) {
                    float p = ex2(ds[nt][e]);
                    if (masked) {
                        int key = kc + (e & 1);
                        int rq  = rowq0 + ((e >> 1) << 3);
                        p = (key <= rq) ? p : 0.f;
                    }
                    ds[nt][e] = p;
                }
            }
            unsigned pa[4];
            pa[0] = packh2(ds[0][1], ds[0][0]);
            pa[1] = packh2(ds[0][3], ds[0][2]);
            pa[2] = packh2(ds[1][1], ds[1][0]);
            pa[3] = packh2(ds[1][3], ds[1][2]);
            mma16816(Dl[mt], pa, ones);
#pragma unroll
            for (int nh = 0; nh < 2; nh++)
                mma16816(Do[mt][nh], pa, vhb[nh]);
        }
    };

    // ---- 3-stage per-warp pipeline (stride = 4 warps x 16 keys) ----
    int t0 = kb + w * 16;
    if (t0 < ke) {
        int pending = 0;
        load_chunk(0, t0); pending++;
        if (t0 + 64 < ke) { load_chunk(1, t0 + 64); pending++; }
        int bf = 0;
        for (; t0 < ke; t0 += 64, bf = (bf == 2 ? 0 : bf + 1)) {
            if (t0 + 128 < ke) {
                load_chunk((bf + 2) % 3, t0 + 128);
                pending++;
            }
            pending--;
            if (pending >= 2)      asm volatile("cp.async.wait_group 2;");
            else if (pending == 1) asm volatile("cp.async.wait_group 1;");
            else                   asm volatile("cp.async.wait_group 0;");
            __syncwarp();
            compute(bf, t0, t0 >= q_start);
            __syncwarp();
        }
    }

    // in-block reduction across the 4 warps
    __syncthreads();
    float* sred = (float*)sbuf;            // [4][32][16]
    float* sl   = (float*)(sbuf + 8192);   // [4][32]
#pragma unroll
    for (int mt = 0; mt < 2; mt++) {
#pragma unroll
        for (int nt = 0; nt < 2; nt++)
#pragma unroll
            for (int e = 0; e < 4; e++) {
                int rl = mt * 16 + g + ((e >> 1) << 3);
                int cl = nt * 8 + tig * 2 + (e & 1);
                sred[(w * 32 + rl) * 16 + cl] = Do[mt][nt][e];
            }
        if (tig == 0) {
            sl[w * 32 + mt * 16 + g]     = Dl[mt][0];
            sl[w * 32 + mt * 16 + g + 8] = Dl[mt][2];
        }
    }
    __syncthreads();

    {
        const int row = tid >> 2;
        const int cg  = tid & 3;
        float4 a = make_float4(0.f, 0.f, 0.f, 0.f);
#pragma unroll
        for (int ww = 0; ww < 4; ww++) {
            float4 t = *(const float4*)&sred[(ww * 32 + row) * 16 + cg * 4];
            a.x += t.x; a.y += t.y; a.z += t.z; a.w += t.w;
        }
        const size_t prow = (size_t)split * BT_ + (size_t)b * T_ + q_start + row;
        ((float4*)(g_pacc + prow * 16))[cg] = a;
        if (cg == 0) {
            float ls = sl[row] + sl[32 + row] + sl[64 + row] + sl[96 + row];
            g_pl[prow] = ls;
        }
    }
}

// ---------------------------------------------------------------------------
// Kernel 3: combine 4 split slots. 8 threads per row (2 splits each),
// shfl-pair merge. 1024 blocks x 128 threads.
// ---------------------------------------------------------------------------
__global__ __launch_bounds__(128)
void combine_kernel(float* __restrict__ out) {
    const int idx = blockIdx.x * 128 + threadIdx.x;   // 0 .. BT_*8-1
    const int row = idx >> 3;
    const int sh  = (idx >> 2) & 1;                   // split half (0: s0,1; 1: s2,3)
    const int cg  = idx & 3;

    float l = 0.f;
    float4 a = make_float4(0.f, 0.f, 0.f, 0.f);
#pragma unroll
    for (int i = 0; i < 2; i++) {
        const int s = sh * 2 + i;
        l += g_pl[(size_t)s * BT_ + row];
        float4 t = ((const float4*)(g_pacc + ((size_t)s * BT_ + row) * 16))[cg];
        a.x += t.x; a.y += t.y; a.z += t.z; a.w += t.w;
    }
    l   += __shfl_xor_sync(0xffffffffu, l, 4);
    a.x += __shfl_xor_sync(0xffffffffu, a.x, 4);
    a.y += __shfl_xor_sync(0xffffffffu, a.y, 4);
    a.z += __shfl_xor_sync(0xffffffffu, a.z, 4);
    a.w += __shfl_xor_sync(0xffffffffu, a.w, 4);

    if (sh == 0) {
        const float inv = 1.0f / l;
        ((float4*)(out + (size_t)row * 16))[cg] =
            make_float4(a.x * inv, a.y * inv, a.z * inv, a.w * inv);
    }
}

extern "C" void kernel_launch(void* const* d_in, const int* in_sizes, int n_in,
                              void* d_out, int out_size) {
    const float* x  = (const float*)d_in[0];
    const float* Wk = (const float*)d_in[1];
    const float* Wq = (const float*)d_in[2];
    const float* Wv = (const float*)d_in[3];
    float* out = (float*)d_out;

    prep_kernel<<<288, 128>>>(Wk, Wq, Wv);
    proj_mma<<<BT_ / 64, 128>>>(x);
    attn_kernel<<<dim3(T_ / 32, SPLITS, B_), 128>>>();
    combine_kernel<<<BT_ * 8 / 128, 128>>>(out);
}

// round 17
// speedup vs baseline: 1.5073x; 1.0065x over previous
#include <cuda_runtime.h>
#include <cuda_fp16.h>
#include <cstdint>

// Problem: B=4, T=4096, C=384 (n_embd), H=16 (head_size)
// out[b,t,:] = softmax_causal( (x@Wq)(x@Wk)^T / sqrt(H) ) @ (x@Wv)

#define B_     4
#define T_     4096
#define C_     384
#define H_     16
#define BT_    (B_ * T_)
#define SPLITS 2

// q keeps hi/lo split (pre-scaled by H^-0.5*log2 e); k, v single fp16 planes.
// q,k: [token][16h]; v: [b][h][t] transposed.
__device__ uint4 g_qh_[BT_ * 2];
__device__ uint4 g_ql_[BT_ * 2];
__device__ uint4 g_kh_[BT_ * 2];
__device__ uint4 g_vh_[B_ * 16 * T_ / 8];
__device__ float g_pacc[(size_t)SPLITS * BT_ * H_];
__device__ float g_pl[SPLITS * BT_];
// W fragments: [kk=24][nt=6][r=2][plane=2][lane=32] fp16x2 (36 KB)
__device__ unsigned g_wfrag[24 * 6 * 2 * 2 * 32];

// ---------------- helpers ----------------
__device__ __forceinline__ float ex2(float x) {
    float y; asm("ex2.approx.ftz.f32 %0, %1;" : "=f"(y) : "f"(x)); return y;
}
__device__ __forceinline__ void cp16(unsigned s, const void* g) {
    asm volatile("cp.async.cg.shared.global [%0], [%1], 16;" :: "r"(s), "l"(g));
}
__device__ __forceinline__ unsigned packh2(float hi, float lo) {
    unsigned r; asm("cvt.rn.f16x2.f32 %0, %1, %2;" : "=r"(r) : "f"(hi), "f"(lo)); return r;
}
__device__ __forceinline__ unsigned pack2h(__half a, __half b) {  // a = lower
    return (unsigned)__half_as_ushort(a) | ((unsigned)__half_as_ushort(b) << 16);
}
__device__ __forceinline__ void split16(float x, __half& hi, __half& lo) {
    hi = __float2half_rn(x);
    lo = __float2half_rn(x - __half2float(hi));
}
__device__ __forceinline__ void mma16816(float* d, const unsigned* a, const unsigned* b) {
    asm volatile(
        "mma.sync.aligned.m16n8k16.row.col.f32.f16.f16.f32 "
        "{%0,%1,%2,%3}, {%4,%5,%6,%7}, {%8,%9}, {%0,%1,%2,%3};"
        : "+f"(d[0]), "+f"(d[1]), "+f"(d[2]), "+f"(d[3])
        : "r"(a[0]), "r"(a[1]), "r"(a[2]), "r"(a[3]), "r"(b[0]), "r"(b[1]));
}

// ---------------------------------------------------------------------------
// Kernel 0: W prep — fragment-exact hi/lo fp16 W tiles. Grid 288.
// ---------------------------------------------------------------------------
__global__ __launch_bounds__(128)
void prep_kernel(const float* __restrict__ Wk,
                 const float* __restrict__ Wq,
                 const float* __restrict__ Wv) {
    const int idx = blockIdx.x * 128 + threadIdx.x;   // 0..36863
    const int lane = idx & 31;
    const int pl = (idx >> 5) & 1;
    const int r  = (idx >> 6) & 1;
    const int rem = idx >> 7;
    const int nt = rem % 6;
    const int kk = rem / 6;
    const int gg = lane >> 2, tg = lane & 3;
    const int n  = nt * 8 + gg;
    const int k0 = kk * 16 + 2 * tg + r * 8;

    const float* Ws = (n < 16) ? Wk : ((n < 32) ? Wq : Wv);
    const int h = n & 15;
    const float s = (n >= 16 && n < 32) ? (0.25f * 1.4426950408889634f) : 1.0f;
    float v0 = Ws[k0 * 16 + h] * s;
    float v1 = Ws[(k0 + 1) * 16 + h] * s;
    __half h0, l0, h1, l1;
    split16(v0, h0, l0); split16(v1, h1, l1);
    g_wfrag[idx] = pl ? pack2h(l0, l1) : pack2h(h0, h1);
}

// ---------------------------------------------------------------------------
// Kernel 1: tensor-core QKV projection (unchanged R16).
// ---------------------------------------------------------------------------
__global__ __launch_bounds__(128, 4)
void proj_mma(const float* __restrict__ x) {
    const int tid  = threadIdx.x;
    const int w    = tid >> 5;
    const int lane = tid & 31;
    const int g    = lane >> 2, tig = lane & 3;
    const int row0 = blockIdx.x * 64 + w * 16;
    const int ra = row0 + g, rb = ra + 8;

    const float* pa = x + (size_t)ra * C_ + 2 * tig;
    const float* pb = x + (size_t)rb * C_ + 2 * tig;

    float D[6][4];
#pragma unroll
    for (int nt = 0; nt < 6; nt++)
#pragma unroll
        for (int e = 0; e < 4; e++) D[nt][e] = 0.f;

    auto loadA = [&](float2* d, int kk) {
        d[0] = *(const float2*)(pa + kk * 16);
        d[1] = *(const float2*)(pb + kk * 16);
        d[2] = *(const float2*)(pa + kk * 16 + 8);
        d[3] = *(const float2*)(pb + kk * 16 + 8);
    };

    float2 c0[4], c1[4], c2[4];
    loadA(c0, 0);
    loadA(c1, 1);
    loadA(c2, 2);

#pragma unroll 3
    for (int kk = 0; kk < 24; kk++) {
        float2 c3[4];
        if (kk + 3 < 24) loadA(c3, kk + 3);

        unsigned ah[4], al[4];
#pragma unroll
        for (int p = 0; p < 4; p++) {
            __half h0, l0, h1, l1;
            split16(c0[p].x, h0, l0);
            split16(c0[p].y, h1, l1);
            ah[p] = pack2h(h0, h1);
            al[p] = pack2h(l0, l1);
        }

        const unsigned* wkb = g_wfrag + kk * 768 + lane;
#pragma unroll
        for (int nt = 0; nt < 6; nt++) {
            const unsigned* wn = wkb + nt * 128;
            unsigned bh[2], bl[2];
            bh[0] = wn[0];   bl[0] = wn[32];
            bh[1] = wn[64];  bl[1] = wn[96];
            mma16816(D[nt], ah, bh);
            mma16816(D[nt], al, bh);
            mma16816(D[nt], ah, bl);
        }
#pragma unroll
        for (int p = 0; p < 4; p++) { c0[p] = c1[p]; c1[p] = c2[p]; c2[p] = c3[p]; }
    }

    // ---- epilogue ----
    const int bb = ra >> 12;
    unsigned* kh = (unsigned*)g_kh_;
    unsigned* qh = (unsigned*)g_qh_;
    unsigned* ql = (unsigned*)g_ql_;
    __half* vh = (__half*)g_vh_;

#pragma unroll
    for (int rr = 0; rr < 2; rr++) {
        const int token = rr ? rb : ra;
        const int e0 = rr * 2;
        __half h0, l0, h1, l1;

        kh[token * 8 + tig]     = packh2(D[0][e0+1], D[0][e0]);
        kh[token * 8 + tig + 4] = packh2(D[1][e0+1], D[1][e0]);

        split16(D[2][e0], h0, l0); split16(D[2][e0+1], h1, l1);
        qh[token * 8 + tig]     = pack2h(h0, h1);
        ql[token * 8 + tig]     = pack2h(l0, l1);
        split16(D[3][e0], h0, l0); split16(D[3][e0+1], h1, l1);
        qh[token * 8 + tig + 4] = pack2h(h0, h1);
        ql[token * 8 + tig + 4] = pack2h(l0, l1);

        const int t = token & (T_ - 1);
#pragma unroll
        for (int nv = 0; nv < 2; nv++) {
            const int hb = bb * 16 + nv * 8 + 2 * tig;
            vh[(size_t)hb * T_ + t]       = __float2half_rn(D[4 + nv][e0]);
            vh[(size_t)(hb + 1) * T_ + t] = __float2half_rn(D[4 + nv][e0+1]);
        }
    }
}

// ---------------------------------------------------------------------------
// Kernel 2: tensor-core causal flash attention. SPLITS=2; occupancy 5.
// Single-plane K/V, 14 MMAs per 16-key chunk, 3-stage per-warp pipeline.
// ---------------------------------------------------------------------------
__global__ __launch_bounds__(128, 5)
void attn_kernel() {
    // per warp: 3 bufs x (kh 768 | vh 768) = 4608 B -> 18432 B total
    __shared__ __align__(16) char sbuf[4 * 4608];

    const int tid  = threadIdx.x;
    const int w    = tid >> 5;
    const int lane = tid & 31;
    const int g    = lane >> 2;
    const int tig  = lane & 3;
    const int b    = blockIdx.z;
    const int split = blockIdx.y;
    const int tile  = (int)gridDim.x - 1 - (int)blockIdx.x;  // heavy-first
    const int q_start = tile * 32;
    const int n_keys = q_start + 32;
    const int len = ((n_keys + 16 * SPLITS - 1) / (16 * SPLITS)) * 16;
    const int kb  = split * len;
    const int ke  = min(kb + len, n_keys);

    unsigned qh[2][4], ql[2][4];
    {
        const char* qhb = (const char*)g_qh_;
        const char* qlb = (const char*)g_ql_;
        const size_t qrow0 = (size_t)b * T_ + q_start;
#pragma unroll
        for (int mt = 0; mt < 2; mt++)
#pragma unroll
            for (int p4 = 0; p4 < 4; p4++) {
                int roff = mt * 16 + g + ((p4 & 1) << 3);
                int hoff = tig * 2 + ((p4 >> 1) << 3);
                size_t off = (qrow0 + roff) * 32 + hoff * 2;
                qh[mt][p4] = *(const unsigned*)(qhb + off);
                ql[mt][p4] = *(const unsigned*)(qlb + off);
            }
    }

    float Do[2][2][4];
    float Dl[2][4];
#pragma unroll
    for (int a = 0; a < 2; a++) {
#pragma unroll
        for (int c = 0; c < 2; c++)
#pragma unroll
            for (int e = 0; e < 4; e++) Do[a][c][e] = 0.f;
#pragma unroll
        for (int e = 0; e < 4; e++) Dl[a][e] = 0.f;
    }
    const unsigned ones[2] = {0x3C003C00u, 0x3C003C00u};   // fp16 1.0 x2

    char* wb = sbuf + w * 4608;
    const __half* khg = (const __half*)g_kh_ + (size_t)b * T_ * 16;
    const __half* vhg = (const __half*)g_vh_ + (size_t)b * 16 * T_;

    auto load_chunk = [&](int bf, int t0) {
        unsigned sa = (unsigned)__cvta_generic_to_shared(wb + bf * 1536);
        const int e = lane >> 1;
        const int hf = lane & 1;
        cp16(sa +       (unsigned)(e * 48 + hf * 16), khg + (size_t)(t0 + e) * 16 + hf * 8);
        cp16(sa + 768u + (unsigned)(e * 48 + hf * 16), vhg + (size_t)e * T_ + t0 + hf * 8);
        asm volatile("cp.async.commit_group;");
    };

    auto compute = [&](int bf, int t0, bool masked) {
        const char* kh_s = wb + bf * 1536;
        const char* vh_s = kh_s + 768;

        unsigned khb[2][2], vhb[2][2];
#pragma unroll
        for (int nt = 0; nt < 2; nt++) {
            int key = g + nt * 8;
            khb[nt][0] = *(const unsigned*)(kh_s + key * 48 + tig * 4);
            khb[nt][1] = *(const unsigned*)(kh_s + key * 48 + 16 + tig * 4);
            int h = g + nt * 8;
            vhb[nt][0] = *(const unsigned*)(vh_s + h * 48 + tig * 4);
            vhb[nt][1] = *(const unsigned*)(vh_s + h * 48 + 16 + tig * 4);
        }

#pragma unroll
        for (int mt = 0; mt < 2; mt++) {
            float ds[2][4];
#pragma unroll
            for (int nt = 0; nt < 2; nt++) {
#pragma unroll
                for (int e = 0; e < 4; e++) ds[nt][e] = 0.f;
                mma16816(ds[nt], qh[mt], khb[nt]);
                mma16816(ds[nt], ql[mt], khb[nt]);
            }
            const int rowq0 = q_start + mt * 16 + g;
#pragma unroll
            for (int nt = 0; nt < 2; nt++) {
                const int kc = t0 + nt * 8 + 2 * tig;
#pragma unroll
                for (int e = 0; e < 4; e++) {
                    float p = ex2(ds[nt][e]);
                    if (masked) {
                        int key = kc + (e & 1);
                        int rq  = rowq0 + ((e >> 1) << 3);
                        p = (key <= rq) ? p : 0.f;
                    }
                    ds[nt][e] = p;
                }
            }
            unsigned pa[4];
            pa[0] = packh2(ds[0][1], ds[0][0]);
            pa[1] = packh2(ds[0][3], ds[0][2]);
            pa[2] = packh2(ds[1][1], ds[1][0]);
            pa[3] = packh2(ds[1][3], ds[1][2]);
            mma16816(Dl[mt], pa, ones);
#pragma unroll
            for (int nh = 0; nh < 2; nh++)
                mma16816(Do[mt][nh], pa, vhb[nh]);
        }
    };

    // ---- 3-stage per-warp pipeline (stride = 4 warps x 16 keys) ----
    int t0 = kb + w * 16;
    if (t0 < ke) {
        int pending = 0;
        load_chunk(0, t0); pending++;
        if (t0 + 64 < ke) { load_chunk(1, t0 + 64); pending++; }
        int bf = 0;
        for (; t0 < ke; t0 += 64, bf = (bf == 2 ? 0 : bf + 1)) {
            if (t0 + 128 < ke) {
                load_chunk((bf + 2) % 3, t0 + 128);
                pending++;
            }
            pending--;
            if (pending >= 2)      asm volatile("cp.async.wait_group 2;");
            else if (pending == 1) asm volatile("cp.async.wait_group 1;");
            else                   asm volatile("cp.async.wait_group 0;");
            __syncwarp();
            compute(bf, t0, t0 >= q_start);
            __syncwarp();
        }
    }

    // in-block reduction across the 4 warps
    __syncthreads();
    float* sred = (float*)sbuf;            // [4][32][16]
    float* sl   = (float*)(sbuf + 8192);   // [4][32]
#pragma unroll
    for (int mt = 0; mt < 2; mt++) {
#pragma unroll
        for (int nt = 0; nt < 2; nt++)
#pragma unroll
            for (int e = 0; e < 4; e++) {
                int rl = mt * 16 + g + ((e >> 1) << 3);
                int cl = nt * 8 + tig * 2 + (e & 1);
                sred[(w * 32 + rl) * 16 + cl] = Do[mt][nt][e];
            }
        if (tig == 0) {
            sl[w * 32 + mt * 16 + g]     = Dl[mt][0];
            sl[w * 32 + mt * 16 + g + 8] = Dl[mt][2];
        }
    }
    __syncthreads();

    {
        const int row = tid >> 2;
        const int cg  = tid & 3;
        float4 a = make_float4(0.f, 0.f, 0.f, 0.f);
#pragma unroll
        for (int ww = 0; ww < 4; ww++) {
            float4 t = *(const float4*)&sred[(ww * 32 + row) * 16 + cg * 4];
            a.x += t.x; a.y += t.y; a.z += t.z; a.w += t.w;
        }
        const size_t prow = (size_t)split * BT_ + (size_t)b * T_ + q_start + row;
        ((float4*)(g_pacc + prow * 16))[cg] = a;
        if (cg == 0) {
            float ls = sl[row] + sl[32 + row] + sl[64 + row] + sl[96 + row];
            g_pl[prow] = ls;
        }
    }
}

// ---------------------------------------------------------------------------
// Kernel 3: combine 2 split slots. 8 threads/row = (2 splits x 4 cgs),
// one LDG.128 + one LDG.32 each, shfl-pair merge.
// ---------------------------------------------------------------------------
__global__ __launch_bounds__(128)
void combine_kernel(float* __restrict__ out) {
    const int idx = blockIdx.x * 128 + threadIdx.x;   // 0 .. BT_*8-1
    const int row = idx >> 3;
    const int s   = (idx >> 2) & 1;                   // split
    const int cg  = idx & 3;

    float l = g_pl[(size_t)s * BT_ + row];
    float4 a = ((const float4*)(g_pacc + ((size_t)s * BT_ + row) * 16))[cg];

    l   += __shfl_xor_sync(0xffffffffu, l, 4);
    a.x += __shfl_xor_sync(0xffffffffu, a.x, 4);
    a.y += __shfl_xor_sync(0xffffffffu, a.y, 4);
    a.z += __shfl_xor_sync(0xffffffffu, a.z, 4);
    a.w += __shfl_xor_sync(0xffffffffu, a.w, 4);

    if (s == 0) {
        const float inv = 1.0f / l;
        ((float4*)(out + (size_t)row * 16))[cg] =
            make_float4(a.x * inv, a.y * inv, a.z * inv, a.w * inv);
    }
}

extern "C" void kernel_launch(void* const* d_in, const int* in_sizes, int n_in,
                              void* d_out, int out_size) {
    const float* x  = (const float*)d_in[0];
    const float* Wk = (const float*)d_in[1];
    const float* Wq = (const float*)d_in[2];
    const float* Wv = (const float*)d_in[3];
    float* out = (float*)d_out;

    prep_kernel<<<288, 128>>>(Wk, Wq, Wv);
    proj_mma<<<BT_ / 64, 128>>>(x);
    attn_kernel<<<dim3(T_ / 32, SPLITS, B_), 128>>>();
    combine_kernel<<<BT_ * 8 / 128, 128>>>(out);
}